// round 1
// baseline (speedup 1.0000x reference)
#include <cuda_runtime.h>
#include <math.h>

#define NN 100000
#define DD 128
#define CC 40
#define EPSBN 1e-5f

// ---- scratch (device globals; no allocations allowed) ----
__device__ float4 g_h4[NN * 32];      // current activations [N,128]
__device__ float4 g_hw4[NN * 32];     // h @ W               [N,128]
__device__ float4 g_agg4[NN * 32];    // aggregated          [N,128]
__device__ float  g_deg[NN];
__device__ float  g_dinv[NN];
__device__ float4 g_colsum4[32];      // 128 col sums
__device__ float4 g_colsumsq4[32];    // 128 col sums of squares

// ---------------- degree / norm ----------------
__global__ void deg_init_k() {
    int i = blockIdx.x * blockDim.x + threadIdx.x;
    if (i < NN) g_deg[i] = 1.0f;   // self-loop
}

__global__ void deg_count_k(const int* __restrict__ dst, int E) {
    int e = blockIdx.x * blockDim.x + threadIdx.x;
    if (e < E) atomicAdd(&g_deg[dst[e]], 1.0f);
}

__global__ void dinv_k() {
    int i = blockIdx.x * blockDim.x + threadIdx.x;
    if (i < NN) g_dinv[i] = rsqrtf(g_deg[i]);   // deg >= 1 always
}

// ---------------- GEMM: C[n,128] = A[n,128] @ B[128,128] (+bias, +relu) ----------------
// 64-row block tile, full 128 cols, full K=128 staged in shared (96KB dynamic).
// 256 threads, each computes a 4x8 micro-tile.
__global__ __launch_bounds__(256) void gemm128_k(
    const float* __restrict__ A, const float* __restrict__ B,
    const float* __restrict__ bias, float* __restrict__ Cout,
    int n, int relu)
{
    extern __shared__ float sm[];
    float* As = sm;             // [64][128]
    float* Bs = sm + 64 * DD;   // [128][128]
    int tid = threadIdx.x;
    int r0 = blockIdx.x * 64;

    {
        const float4* B4 = (const float4*)B;
        float4* Bs4 = (float4*)Bs;
#pragma unroll
        for (int i = 0; i < 16; i++) Bs4[tid + i * 256] = B4[tid + i * 256];

        const float4* A4 = (const float4*)A;
        float4* As4 = (float4*)As;
#pragma unroll
        for (int i = 0; i < 8; i++) {
            int j = tid + i * 256;
            int r = j >> 5;
            float4 v = make_float4(0.f, 0.f, 0.f, 0.f);
            if (r0 + r < n) v = A4[(size_t)(r0 + r) * 32 + (j & 31)];
            As4[j] = v;
        }
    }
    __syncthreads();

    int ty = tid >> 4, tx = tid & 15;
    const float* Ab = As + ty * 4 * DD;
    const float* Bb = Bs + tx * 8;

    float acc[4][8];
#pragma unroll
    for (int i = 0; i < 4; i++)
#pragma unroll
        for (int j = 0; j < 8; j++) acc[i][j] = 0.f;

#pragma unroll 4
    for (int k = 0; k < DD; k++) {
        float4 b0 = *(const float4*)(Bb + k * DD);
        float4 b1 = *(const float4*)(Bb + k * DD + 4);
        float bv[8] = {b0.x, b0.y, b0.z, b0.w, b1.x, b1.y, b1.z, b1.w};
        float av[4] = {Ab[k], Ab[DD + k], Ab[2 * DD + k], Ab[3 * DD + k]};
#pragma unroll
        for (int i = 0; i < 4; i++)
#pragma unroll
            for (int j = 0; j < 8; j++) acc[i][j] += av[i] * bv[j];
    }

    float biasv[8];
#pragma unroll
    for (int j = 0; j < 8; j++) biasv[j] = bias ? __ldg(&bias[tx * 8 + j]) : 0.f;

#pragma unroll
    for (int i = 0; i < 4; i++) {
        int r = r0 + ty * 4 + i;
        if (r < n) {
            float o[8];
#pragma unroll
            for (int j = 0; j < 8; j++) {
                float v = acc[i][j] + biasv[j];
                o[j] = relu ? fmaxf(v, 0.f) : v;
            }
            float4* Cr = (float4*)(Cout + (size_t)r * DD);
            Cr[tx * 2]     = make_float4(o[0], o[1], o[2], o[3]);
            Cr[tx * 2 + 1] = make_float4(o[4], o[5], o[6], o[7]);
        }
    }
}

// ---------------- self-loop init + zero BN accumulators ----------------
__global__ void agg_init_k(const float4* __restrict__ hw, float4* __restrict__ agg) {
    if (blockIdx.x == 0 && threadIdx.x < DD) {
        ((float*)g_colsum4)[threadIdx.x] = 0.f;
        ((float*)g_colsumsq4)[threadIdx.x] = 0.f;
    }
    int idx = blockIdx.x * blockDim.x + threadIdx.x;
    if (idx >= NN * 32) return;
    int i = idx >> 5;
    float di = g_dinv[i];
    float w = di * di;
    float4 v = hw[idx];
    v.x *= w; v.y *= w; v.z *= w; v.w *= w;
    agg[idx] = v;
}

// ---------------- edge scatter: one warp per edge, vector red ----------------
__global__ void scatter_k(const float4* __restrict__ hw, const int* __restrict__ src,
                          const int* __restrict__ dst, float* __restrict__ agg, int E)
{
    int idx = blockIdx.x * blockDim.x + threadIdx.x;
    int e = idx >> 5;
    if (e >= E) return;
    int lane = idx & 31;
    int s = 0, d = 0; float w = 0.f;
    if (lane == 0) {
        s = __ldg(&src[e]);
        d = __ldg(&dst[e]);
        w = g_dinv[s] * g_dinv[d];
    }
    s = __shfl_sync(0xffffffff, s, 0);
    d = __shfl_sync(0xffffffff, d, 0);
    w = __shfl_sync(0xffffffff, w, 0);
    float4 v = hw[(size_t)s * 32 + lane];
    float* p = agg + (size_t)d * DD + lane * 4;
    asm volatile("red.global.add.v4.f32 [%0], {%1, %2, %3, %4};"
                 :: "l"(p), "f"(v.x * w), "f"(v.y * w), "f"(v.z * w), "f"(v.w * w)
                 : "memory");
}

// ---------------- BatchNorm column stats ----------------
__global__ void bn_stats_k(const float* __restrict__ agg) {
    int c = threadIdx.x;   // 128 threads = 128 columns
    float s = 0.f, s2 = 0.f;
    for (int r = blockIdx.x; r < NN; r += gridDim.x) {
        float v = agg[(size_t)r * DD + c];
        s += v; s2 += v * v;
    }
    atomicAdd(&((float*)g_colsum4)[c], s);
    atomicAdd(&((float*)g_colsumsq4)[c], s2);
}

// ---------------- BN apply + PReLU (optionally also write embeddings out) ----------------
__global__ void bn_apply_k(const float4* __restrict__ agg,
                           const float* __restrict__ gamma, const float* __restrict__ beta,
                           const float* __restrict__ pa, int l,
                           float4* __restrict__ outA, float4* __restrict__ outB)
{
    int idx = blockIdx.x * blockDim.x + threadIdx.x;
    if (idx >= NN * 32) return;
    int c4 = idx & 31;
    const float invN = 1.0f / NN;
    float4 v  = agg[idx];
    float4 s  = g_colsum4[c4];
    float4 s2 = g_colsumsq4[c4];
    float4 g  = ((const float4*)gamma)[c4];
    float4 be = ((const float4*)beta)[c4];
    float a = __ldg(&pa[l]);

    float mu, var, rs, h;
    float4 o;
    mu = s.x * invN;  var = s2.x * invN - mu * mu;  rs = rsqrtf(var + EPSBN);
    h = (v.x - mu) * rs * g.x + be.x;  o.x = h > 0.f ? h : a * h;
    mu = s.y * invN;  var = s2.y * invN - mu * mu;  rs = rsqrtf(var + EPSBN);
    h = (v.y - mu) * rs * g.y + be.y;  o.y = h > 0.f ? h : a * h;
    mu = s.z * invN;  var = s2.z * invN - mu * mu;  rs = rsqrtf(var + EPSBN);
    h = (v.z - mu) * rs * g.z + be.z;  o.z = h > 0.f ? h : a * h;
    mu = s.w * invN;  var = s2.w * invN - mu * mu;  rs = rsqrtf(var + EPSBN);
    h = (v.w - mu) * rs * g.w + be.w;  o.w = h > 0.f ? h : a * h;

    outA[idx] = o;
    if (outB) outB[idx] = o;
}

// ---------------- head: logits = T @ Wh2 + bh2, plus argmax (first-index ties) ----------------
__global__ void head2_k(const float* __restrict__ T, const float* __restrict__ Wh2,
                        const float* __restrict__ bh2, float* __restrict__ logits,
                        float* __restrict__ amax)
{
    __shared__ float Wsh[DD * CC];
    __shared__ float bsh[CC];
    __shared__ __align__(16) float rows[8][DD];
    int tid = threadIdx.x;
    for (int i = tid; i < DD * CC; i += 256) Wsh[i] = Wh2[i];
    if (tid < CC) bsh[tid] = bh2[tid];
    __syncthreads();

    int w = tid >> 5, lane = tid & 31;
    int r = blockIdx.x * 8 + w;
    if (r >= NN) return;

    ((float4*)rows[w])[lane] = ((const float4*)T)[(size_t)r * 32 + lane];
    __syncwarp();

    int c1 = lane + 32;
    bool has2 = c1 < CC;
    int c1c = has2 ? c1 : (CC - 1);
    float acc0 = bsh[lane];
    float acc1 = bsh[c1c];
    const float* rw = rows[w];
#pragma unroll 8
    for (int k = 0; k < DD; k++) {
        float t = rw[k];
        acc0 += t * Wsh[k * CC + lane];
        acc1 += t * Wsh[k * CC + c1c];
    }
    logits[(size_t)r * CC + lane] = acc0;
    if (has2) logits[(size_t)r * CC + c1] = acc1;

    float bv = acc0; int bi = lane;
    if (has2 && acc1 > bv) { bv = acc1; bi = c1; }
#pragma unroll
    for (int off = 16; off > 0; off >>= 1) {
        float ov = __shfl_down_sync(0xffffffff, bv, off);
        int   oi = __shfl_down_sync(0xffffffff, bi, off);
        if (ov > bv || (ov == bv && oi < bi)) { bv = ov; bi = oi; }
    }
    if (lane == 0) amax[r] = (float)bi;
}

// ---------------- launch ----------------
extern "C" void kernel_launch(void* const* d_in, const int* in_sizes, int n_in,
                              void* d_out, int out_size)
{
    const float* x      = (const float*)d_in[0];
    const int*   ei     = (const int*)d_in[1];
    const float* Ws     = (const float*)d_in[2];
    // d_in[3] = bs (bias): per-column constant, cancels exactly under training-mode BN
    const float* gammas = (const float*)d_in[4];
    const float* betas  = (const float*)d_in[5];
    const float* pa     = (const float*)d_in[6];
    const float* Wh1    = (const float*)d_in[7];
    const float* bh1    = (const float*)d_in[8];
    const float* Wh2    = (const float*)d_in[9];
    const float* bh2    = (const float*)d_in[10];
    float* out = (float*)d_out;

    int E = in_sizes[1] / 2;
    const int* srcp = ei;
    const int* dstp = ei + E;

    cudaFuncSetAttribute(gemm128_k, cudaFuncAttributeMaxDynamicSharedMemorySize, 98304);

    void *ph, *phw, *pagg;
    cudaGetSymbolAddress(&ph,   g_h4);
    cudaGetSymbolAddress(&phw,  g_hw4);
    cudaGetSymbolAddress(&pagg, g_agg4);
    float4* hbuf = (float4*)ph;
    float4* hw   = (float4*)phw;
    float4* agg  = (float4*)pagg;

    const int EW = 32;                        // lanes per edge
    int nblk_elem = (NN * 32 + 255) / 256;    // 12500
    int nblk_gemm = (NN + 63) / 64;           // 1563

    deg_init_k<<<(NN + 255) / 256, 256>>>();
    deg_count_k<<<(E + 255) / 256, 256>>>(dstp, E);
    dinv_k<<<(NN + 255) / 256, 256>>>();

    const float* hin = x;
    for (int l = 0; l < 3; l++) {
        gemm128_k<<<nblk_gemm, 256, 98304>>>(hin, Ws + (size_t)l * DD * DD,
                                             nullptr, (float*)hw, NN, 0);
        agg_init_k<<<nblk_elem, 256>>>(hw, agg);
        scatter_k<<<((size_t)E * EW + 255) / 256, 256>>>(hw, srcp, dstp, (float*)agg, E);
        bn_stats_k<<<512, 128>>>((const float*)agg);
        bn_apply_k<<<nblk_elem, 256>>>(agg, gammas + (size_t)l * DD, betas + (size_t)l * DD,
                                       pa, l, hbuf,
                                       (l == 2) ? (float4*)out : nullptr);
        hin = (const float*)hbuf;
    }

    // head: relu(h @ Wh1 + bh1) -> g_hw, then logits + argmax
    gemm128_k<<<nblk_gemm, 256, 98304>>>((const float*)hbuf, Wh1, bh1, (float*)hw, NN, 1);
    head2_k<<<(NN + 7) / 8, 256>>>((const float*)hw, Wh2, bh2,
                                   out + (size_t)NN * DD,
                                   out + (size_t)NN * (DD + CC));
}